// round 11
// baseline (speedup 1.0000x reference)
#include <cuda_runtime.h>
#include <cstdint>

#define BLOCK   256
#define ROWS    512            // rows per tile; 2560 floats input + 512 targets
#define STAGES  3
#define NBLOCKS 888            // 148 SMs * 6 blocks (36KB smem each)

__device__ float g_partials[NBLOCKS];
__device__ unsigned int g_count = 0;

__device__ __forceinline__ void cp16(uint32_t smem_addr, const void* gptr) {
    asm volatile("cp.async.cg.shared.global [%0], [%1], 16;"
                 :: "r"(smem_addr), "l"(gptr));
}
__device__ __forceinline__ void cp_commit() {
    asm volatile("cp.async.commit_group;");
}
template <int N>
__device__ __forceinline__ void cp_wait() {
    asm volatile("cp.async.wait_group %0;" :: "n"(N));
}

__global__ void __launch_bounds__(BLOCK)
loss_kernel(const float* __restrict__ in,
            const float* __restrict__ tgt,
            long long nrows,
            float* __restrict__ out)
{
    __shared__ __align__(16) float s_in[STAGES][ROWS * 5];
    __shared__ __align__(16) float s_t[STAGES][ROWS];

    const int tid = threadIdx.x;
    const long long fulltiles = nrows / ROWS;
    float acc = 0.0f;

    // Contiguous per-block tile range: block b owns [tbeg, tend).
    const long long base = fulltiles / gridDim.x;
    const long long rem  = fulltiles % gridDim.x;
    const long long b    = blockIdx.x;
    const long long tbeg = b * base + min(b, rem);
    const long long tend = tbeg + base + (b < rem ? 1 : 0);

    // Tail rows (nrows % ROWS) handled by block 0 directly.
    if (blockIdx.x == 0) {
        for (long long r = fulltiles * ROWS + tid; r < nrows; r += BLOCK) {
            const float x0 = in[r * 5 + 0];
            const float x2 = in[r * 5 + 2];
            const float x4 = in[r * 5 + 4];
            const float t  = tgt[r];
            const float d  = (fabsf(x4 - x2) < 0.1f) ? (x0 - x4) : (x0 - t);
            acc += fabsf(d);
        }
    }

    auto stage = [&](int slot, long long tile) {
        if (tile < tend) {
            const float4* __restrict__ src =
                reinterpret_cast<const float4*>(in + tile * (long long)ROWS * 5);
            const uint32_t sb = (uint32_t)__cvta_generic_to_shared(&s_in[slot][0]);
            #pragma unroll
            for (int k = 0; k < 3; k++) {
                const int i = tid + k * BLOCK;
                if (i < (ROWS * 5) / 4)                      // 640 float4
                    cp16(sb + (uint32_t)i * 16, src + i);
            }
            if (tid < ROWS / 4) {                            // 128 float4
                const float4* __restrict__ tsrc =
                    reinterpret_cast<const float4*>(tgt + tile * ROWS);
                cp16((uint32_t)__cvta_generic_to_shared(&s_t[slot][0]) +
                         (uint32_t)tid * 16,
                     tsrc + tid);
            }
        }
        cp_commit();
    };

    #pragma unroll
    for (int k = 0; k < STAGES; k++)
        stage(k, tbeg + k);

    int cnt = 0;
    for (long long t = tbeg; t < tend; t++, cnt++) {
        const int slot = cnt % STAGES;
        cp_wait<STAGES - 2>();   // current slot's group complete
        __syncthreads();         // smem visible; prev slot fully consumed by all

        if (cnt > 0) {           // refill the slot consumed last iteration
            const int prev = (slot + STAGES - 1) % STAGES;
            stage(prev, t + (STAGES - 1));
        }

        #pragma unroll
        for (int j = 0; j < ROWS / BLOCK; j++) {
            const int r = tid + j * BLOCK;
            const float x0 = s_in[slot][r * 5 + 0];
            const float x2 = s_in[slot][r * 5 + 2];
            const float x4 = s_in[slot][r * 5 + 4];
            const float tv = s_t[slot][r];
            const float d  = (fabsf(x4 - x2) < 0.1f) ? (x0 - x4) : (x0 - tv);
            acc += fabsf(d);
        }
    }
    cp_wait<0>();
    __syncthreads();

    // Block reduction (reuse s_t[0] as scratch — pipeline drained).
    #pragma unroll
    for (int off = 16; off > 0; off >>= 1)
        acc += __shfl_down_sync(0xFFFFFFFFu, acc, off);
    if ((tid & 31) == 0) s_t[0][tid >> 5] = acc;
    __syncthreads();

    __shared__ int s_last;
    if (tid == 0) {
        float v = 0.0f;
        #pragma unroll
        for (int w = 0; w < BLOCK / 32; w++) v += s_t[0][w];
        g_partials[blockIdx.x] = v;
        __threadfence();
        const unsigned int old = atomicAdd(&g_count, 1u);
        s_last = (old == gridDim.x - 1);
    }
    __syncthreads();

    // Last block: deterministic double-precision final reduce.
    if (s_last) {
        double* sd = reinterpret_cast<double*>(&s_in[0][0]);  // 16B-aligned
        double a = 0.0;
        for (int i = tid; i < NBLOCKS; i += BLOCK)
            a += (double)g_partials[i];
        #pragma unroll
        for (int off = 16; off > 0; off >>= 1)
            a += __shfl_down_sync(0xFFFFFFFFu, a, off);
        if ((tid & 31) == 0) sd[tid >> 5] = a;
        __syncthreads();
        if (tid == 0) {
            double s = 0.0;
            #pragma unroll
            for (int w = 0; w < BLOCK / 32; w++) s += sd[w];
            out[0] = (float)(s / (double)nrows);
            g_count = 0;    // reset for next graph replay (determinism)
        }
    }
}

extern "C" void kernel_launch(void* const* d_in, const int* in_sizes, int n_in,
                              void* d_out, int out_size)
{
    const float* inputs  = (const float*)d_in[0];   // [N, 5] fp32
    const float* targets = (const float*)d_in[1];   // [N, 1] fp32
    float* out = (float*)d_out;

    const long long nrows = (long long)in_sizes[0] / 5;

    loss_kernel<<<NBLOCKS, BLOCK>>>(inputs, targets, nrows, out);
}

// round 12
// speedup vs baseline: 1.0220x; 1.0220x over previous
#include <cuda_runtime.h>
#include <cstdint>

#define BLOCK 256
#define ROWS  1024           // rows per tile; 5120 floats = 1280 float4
#define NBLOCKS 592          // 148 SMs * 4 blocks (exactly 48KB static smem)

__device__ float g_partials[NBLOCKS];
__device__ unsigned int g_count = 0;

__device__ __forceinline__ void cp16(uint32_t smem_addr, const void* gptr) {
    asm volatile("cp.async.cg.shared.global [%0], [%1], 16;"
                 :: "r"(smem_addr), "l"(gptr));
}
__device__ __forceinline__ void cp_commit() {
    asm volatile("cp.async.commit_group;");
}
template <int N>
__device__ __forceinline__ void cp_wait() {
    asm volatile("cp.async.wait_group %0;" :: "n"(N));
}

__global__ void __launch_bounds__(BLOCK)
loss_kernel(const float* __restrict__ in,
            const float* __restrict__ tgt,
            long long nrows,
            float* __restrict__ out)
{
    __shared__ __align__(16) float s_in[2][ROWS * 5];
    __shared__ __align__(16) float s_t[2][ROWS];

    const int tid = threadIdx.x;
    const long long fulltiles = nrows / ROWS;
    const long long step = gridDim.x;
    float acc = 0.0f;

    // Tail rows (nrows % ROWS, < 1024) handled directly by block 0.
    if (blockIdx.x == 0) {
        for (long long r = fulltiles * ROWS + tid; r < nrows; r += BLOCK) {
            const float x0 = in[r * 5 + 0];
            const float x2 = in[r * 5 + 2];
            const float x4 = in[r * 5 + 4];
            const float t  = tgt[r];
            const float d  = (fabsf(x4 - x2) < 0.1f) ? (x0 - x4) : (x0 - t);
            acc += fabsf(d);
        }
    }

    // Stage one tile into buffer `buf` via cp.async. Always commits a group
    // (possibly empty) so wait_group counting stays uniform.
    auto stage = [&](int buf, long long tile) {
        if (tile < fulltiles) {
            const float* src = in + tile * (long long)ROWS * 5;
            const uint32_t sbase = (uint32_t)__cvta_generic_to_shared(&s_in[buf][0]);
            #pragma unroll
            for (int i = 0; i < 5; i++)
                cp16(sbase + (uint32_t)(tid + i * BLOCK) * 16,
                     src + (size_t)(tid + i * BLOCK) * 4);
            const uint32_t tbase = (uint32_t)__cvta_generic_to_shared(&s_t[buf][0]);
            cp16(tbase + (uint32_t)tid * 16, tgt + tile * ROWS + (size_t)tid * 4);
        }
        cp_commit();
    };

    const long long t0 = blockIdx.x;
    stage(0, t0);
    stage(1, t0 + step);

    int buf = 0;
    for (long long t = t0; t < fulltiles; t += step) {
        cp_wait<1>();        // current buffer's group complete
        __syncthreads();     // make its smem visible to all threads

        #pragma unroll
        for (int j = 0; j < ROWS / BLOCK; j++) {
            const int r = tid + j * BLOCK;
            const float x0 = s_in[buf][r * 5 + 0];
            const float x2 = s_in[buf][r * 5 + 2];
            const float x4 = s_in[buf][r * 5 + 4];
            const float tv = s_t[buf][r];
            const float d  = (fabsf(x4 - x2) < 0.1f) ? (x0 - x4) : (x0 - tv);
            acc += fabsf(d);
        }

        __syncthreads();     // all threads done reading before refill
        stage(buf, t + 2 * step);
        buf ^= 1;
    }
    cp_wait<0>();            // drain remaining (possibly empty) groups
    __syncthreads();

    // Block reduction (reuse s_t[0] as scratch — pipeline is done).
    #pragma unroll
    for (int off = 16; off > 0; off >>= 1)
        acc += __shfl_down_sync(0xFFFFFFFFu, acc, off);
    if ((tid & 31) == 0) s_t[0][tid >> 5] = acc;
    __syncthreads();

    __shared__ int s_last;
    if (tid == 0) {
        float v = 0.0f;
        #pragma unroll
        for (int w = 0; w < BLOCK / 32; w++) v += s_t[0][w];
        g_partials[blockIdx.x] = v;
        __threadfence();
        const unsigned int old = atomicAdd(&g_count, 1u);
        s_last = (old == gridDim.x - 1);
    }
    __syncthreads();

    // Last block to finish: deterministic double-precision final reduce.
    if (s_last) {
        double* sd = reinterpret_cast<double*>(&s_in[0][0]);  // 16B-aligned
        double a = 0.0;
        for (int i = tid; i < NBLOCKS; i += BLOCK)
            a += (double)g_partials[i];
        #pragma unroll
        for (int off = 16; off > 0; off >>= 1)
            a += __shfl_down_sync(0xFFFFFFFFu, a, off);
        if ((tid & 31) == 0) sd[tid >> 5] = a;
        __syncthreads();
        if (tid == 0) {
            double s = 0.0;
            #pragma unroll
            for (int w = 0; w < BLOCK / 32; w++) s += sd[w];
            out[0] = (float)(s / (double)nrows);
            g_count = 0;    // reset for next graph replay (determinism)
        }
    }
}

extern "C" void kernel_launch(void* const* d_in, const int* in_sizes, int n_in,
                              void* d_out, int out_size)
{
    const float* inputs  = (const float*)d_in[0];   // [N, 5] fp32
    const float* targets = (const float*)d_in[1];   // [N, 1] fp32
    float* out = (float*)d_out;

    const long long nrows = (long long)in_sizes[0] / 5;

    loss_kernel<<<NBLOCKS, BLOCK>>>(inputs, targets, nrows, out);
}

// round 13
// speedup vs baseline: 1.0277x; 1.0056x over previous
#include <cuda_runtime.h>
#include <cstdint>

#define BLOCK 256
#define ROWS  1024           // rows per tile; 5120 input floats = 1280 float4
#define NBLOCKS 740          // 148 SMs * 5 blocks (40KB static smem each)

__device__ float g_partials[NBLOCKS];
__device__ unsigned int g_count = 0;

__device__ __forceinline__ void cp16(uint32_t smem_addr, const void* gptr) {
    asm volatile("cp.async.cg.shared.global [%0], [%1], 16;"
                 :: "r"(smem_addr), "l"(gptr));
}
__device__ __forceinline__ void cp_commit() {
    asm volatile("cp.async.commit_group;");
}
template <int N>
__device__ __forceinline__ void cp_wait() {
    asm volatile("cp.async.wait_group %0;" :: "n"(N));
}

__global__ void __launch_bounds__(BLOCK)
loss_kernel(const float* __restrict__ in,
            const float* __restrict__ tgt,
            long long nrows,
            float* __restrict__ out)
{
    __shared__ __align__(16) float s_in[2][ROWS * 5];   // 40960 bytes
    __shared__ float s_red[BLOCK / 32];

    const int tid = threadIdx.x;
    const long long fulltiles = nrows / ROWS;
    const long long step = gridDim.x;
    float acc = 0.0f;

    // Tail rows (nrows % ROWS) handled directly by block 0.
    if (blockIdx.x == 0) {
        for (long long r = fulltiles * ROWS + tid; r < nrows; r += BLOCK) {
            const float x0 = in[r * 5 + 0];
            const float x2 = in[r * 5 + 2];
            const float x4 = in[r * 5 + 4];
            const float t  = tgt[r];
            const float d  = (fabsf(x4 - x2) < 0.1f) ? (x0 - x4) : (x0 - t);
            acc += fabsf(d);
        }
    }

    // Stage only the inputs tile via cp.async (targets read directly, coalesced).
    auto stage = [&](int buf, long long tile) {
        if (tile < fulltiles) {
            const float* src = in + tile * (long long)ROWS * 5;
            const uint32_t sbase = (uint32_t)__cvta_generic_to_shared(&s_in[buf][0]);
            #pragma unroll
            for (int i = 0; i < 5; i++)
                cp16(sbase + (uint32_t)(tid + i * BLOCK) * 16,
                     src + (size_t)(tid + i * BLOCK) * 4);
        }
        cp_commit();
    };

    const long long t0 = blockIdx.x;
    stage(0, t0);
    stage(1, t0 + step);

    int buf = 0;
    for (long long t = t0; t < fulltiles; t += step) {
        cp_wait<1>();        // current buffer's group complete
        __syncthreads();     // make its smem visible to all threads

        // Issue all 4 coalesced target loads up-front (independent, MLP=4).
        const float* trow = tgt + t * ROWS;
        float tv[ROWS / BLOCK];
        #pragma unroll
        for (int j = 0; j < ROWS / BLOCK; j++)
            tv[j] = __ldg(trow + tid + j * BLOCK);

        #pragma unroll
        for (int j = 0; j < ROWS / BLOCK; j++) {
            const int r = tid + j * BLOCK;
            const float x0 = s_in[buf][r * 5 + 0];
            const float x2 = s_in[buf][r * 5 + 2];
            const float x4 = s_in[buf][r * 5 + 4];
            const float d  = (fabsf(x4 - x2) < 0.1f) ? (x0 - x4) : (x0 - tv[j]);
            acc += fabsf(d);
        }

        __syncthreads();     // all threads done reading before refill
        stage(buf, t + 2 * step);
        buf ^= 1;
    }
    cp_wait<0>();            // drain remaining (possibly empty) groups
    __syncthreads();

    // Block reduction.
    #pragma unroll
    for (int off = 16; off > 0; off >>= 1)
        acc += __shfl_down_sync(0xFFFFFFFFu, acc, off);
    if ((tid & 31) == 0) s_red[tid >> 5] = acc;
    __syncthreads();

    __shared__ int s_last;
    if (tid == 0) {
        float v = 0.0f;
        #pragma unroll
        for (int w = 0; w < BLOCK / 32; w++) v += s_red[w];
        g_partials[blockIdx.x] = v;
        __threadfence();
        const unsigned int old = atomicAdd(&g_count, 1u);
        s_last = (old == gridDim.x - 1);
    }
    __syncthreads();

    // Last block to finish: deterministic double-precision final reduce.
    if (s_last) {
        double* sd = reinterpret_cast<double*>(&s_in[0][0]);  // 16B-aligned
        double a = 0.0;
        for (int i = tid; i < NBLOCKS; i += BLOCK)
            a += (double)g_partials[i];
        #pragma unroll
        for (int off = 16; off > 0; off >>= 1)
            a += __shfl_down_sync(0xFFFFFFFFu, a, off);
        if ((tid & 31) == 0) sd[tid >> 5] = a;
        __syncthreads();
        if (tid == 0) {
            double s = 0.0;
            #pragma unroll
            for (int w = 0; w < BLOCK / 32; w++) s += sd[w];
            out[0] = (float)(s / (double)nrows);
            g_count = 0;    // reset for next graph replay (determinism)
        }
    }
}

extern "C" void kernel_launch(void* const* d_in, const int* in_sizes, int n_in,
                              void* d_out, int out_size)
{
    const float* inputs  = (const float*)d_in[0];   // [N, 5] fp32
    const float* targets = (const float*)d_in[1];   // [N, 1] fp32
    float* out = (float*)d_out;

    const long long nrows = (long long)in_sizes[0] / 5;

    loss_kernel<<<NBLOCKS, BLOCK>>>(inputs, targets, nrows, out);
}